// round 15
// baseline (speedup 1.0000x reference)
#include <cuda_runtime.h>
#include <cstddef>

using ull = unsigned long long;

// Problem constants
constexpr int B_   = 64;
constexpr int T_   = 2048;
constexpr int H_   = 100;
constexpr int IN_  = 10;
constexpr int OUT_ = 10;
constexpr int L_   = 5;
constexpr int M_   = B_ * T_;          // 131072 rows
constexpr int BUF_ELEMS = M_ * H_;     // 52.4 MB

constexpr int TC_  = 64;               // timesteps per chunk
constexpr int NC_  = T_ / TC_;         // 32 chunks

// Scratch (device globals: no allocation anywhere)
__device__ float g_xp0[BUF_ELEMS];                   // precomputed layer-0 xp
__device__ float g_xpc[2 * L_ * B_ * TC_ * H_];      // xp chunks, parity by c&1
__device__ int   g_prodF[L_ * B_];                   // chunks produced for layer li
__device__ int   g_consF[L_ * B_];                   // chunks consumed by layer li

// ---------------------------------------------------------------------------
// Packed f32x2 helpers (sm_103a FFMA2/FADD2 via PTX)
// ---------------------------------------------------------------------------
__device__ __forceinline__ ull ffma2(ull a, ull b, ull c) {
    ull d;
    asm("fma.rn.f32x2 %0, %1, %2, %3;" : "=l"(d) : "l"(a), "l"(b), "l"(c));
    return d;
}
__device__ __forceinline__ ull addf2(ull a, ull b) {
    ull d;
    asm("add.rn.f32x2 %0, %1, %2;" : "=l"(d) : "l"(a), "l"(b));
    return d;
}
__device__ __forceinline__ ull pack2(float lo, float hi) {
    ull r;
    asm("mov.b64 %0, {%1, %2};" : "=l"(r) : "f"(lo), "f"(hi));
    return r;
}
__device__ __forceinline__ float lo2(ull v) {
    return __uint_as_float((unsigned)(v & 0xFFFFFFFFull));
}
__device__ __forceinline__ float hi2(ull v) {
    return __uint_as_float((unsigned)(v >> 32));
}

// ---------------------------------------------------------------------------
// Short-chain overflow-safe tanh: tanh(x) = 1 - 2/(e^{2x}+1).
//   x->+inf: e=inf -> rcp=0 -> 1.  x->-inf: e=0 -> rcp=1 -> -1.  ~1e-6 acc.
// ---------------------------------------------------------------------------
__device__ __forceinline__ float fast_tanh(float x) {
    float t = x * 2.8853900817779268f;     // 2*log2(e)*x
    float e, r;
    asm("ex2.approx.f32 %0, %1;" : "=f"(e) : "f"(t));
    asm("rcp.approx.f32 %0, %1;" : "=f"(r) : "f"(e + 1.0f));
    return fmaf(-2.0f, r, 1.0f);
}

// Batched dot over 100 floats: operands smem (broadcast), weights in regs.
__device__ __forceinline__ float dot100(const ulonglong2* __restrict__ hp,
                                        const ulonglong2* __restrict__ w,
                                        ull a0) {
    ull a1 = 0ull, a2 = 0ull, a3 = 0ull;
    ulonglong2 hv[13];
    #pragma unroll
    for (int i = 0; i < 13; i++) hv[i] = hp[i];
    #pragma unroll
    for (int i = 0; i < 13; i++) {
        if (i & 1) { a2 = ffma2(w[i].x, hv[i].x, a2);
                     a3 = ffma2(w[i].y, hv[i].y, a3); }
        else       { a0 = ffma2(w[i].x, hv[i].x, a0);
                     a1 = ffma2(w[i].y, hv[i].y, a1); }
    }
    #pragma unroll
    for (int i = 0; i < 12; i++) hv[i] = hp[13 + i];
    #pragma unroll
    for (int i = 0; i < 12; i++) {
        if (i & 1) { a3 = ffma2(w[13 + i].x, hv[i].x, a3);
                     a2 = ffma2(w[13 + i].y, hv[i].y, a2); }
        else       { a1 = ffma2(w[13 + i].x, hv[i].x, a1);
                     a0 = ffma2(w[13 + i].y, hv[i].y, a0); }
    }
    const ull s = addf2(addf2(a0, a2), addf2(a1, a3));
    return lo2(s) + hi2(s);
}

// ---------------------------------------------------------------------------
// Init: zero the pipeline flags (runs at the head of every replay).
// ---------------------------------------------------------------------------
__global__ void init_k()
{
    const int i = threadIdx.x;
    if (i < L_ * B_) { g_prodF[i] = 0; g_consF[i] = 0; }
}

// ---------------------------------------------------------------------------
// Prologue: layer-0 input GEMM over the ENTIRE sequence (depends only on x).
// ---------------------------------------------------------------------------
__global__ void __launch_bounds__(256)
gemm0_k(const float* __restrict__ A, const float* __restrict__ W,
        const float* __restrict__ b1, const float* __restrict__ b2,
        float* __restrict__ C)
{
    __shared__ __align__(16) float Ws[H_ * IN_];
    __shared__ __align__(16) float As[16 * IN_];

    for (int i = threadIdx.x; i < H_ * IN_; i += 256) Ws[i] = W[i];

    const int c = threadIdx.x & 127;
    const int g = threadIdx.x >> 7;
    const bool act = (c < H_);
    const float bias = act ? (b1[c] + b2[c]) : 0.0f;

    const int tilesTotal = M_ / 16;
    for (int tile = blockIdx.x; tile < tilesTotal; tile += gridDim.x) {
        __syncthreads();
        const float* Arow = A + (size_t)tile * 16 * IN_;
        for (int i = threadIdx.x; i < 16 * IN_; i += 256) As[i] = Arow[i];
        __syncthreads();

        if (act) {
            float acc[8];
            #pragma unroll
            for (int r = 0; r < 8; r++) acc[r] = bias;
            #pragma unroll
            for (int k = 0; k < IN_; k++) {
                const float wv = Ws[c * IN_ + k];
                #pragma unroll
                for (int r = 0; r < 8; r++)
                    acc[r] += wv * As[(g + 2 * r) * IN_ + k];
            }
            #pragma unroll
            for (int r = 0; r < 8; r++)
                C[(size_t)(tile * 16 + g + 2 * r) * H_ + c] = acc[r];
        }
    }
}

// ---------------------------------------------------------------------------
// Persistent pipeline kernel (R13 skeleton + fused proj + LDG-prefetched xp).
// 320 CTAs (li = bid>>6, b = bid&63) x 128 threads; each owns (li,b) for all
// 32 chunks. Per chunk c:
//   acquire: [li>0] wait prodF[li] >= c+1 (xp chunk ready in xpc slot c&1).
//   scan: 64 steps; xp read via per-step LDG with 2-step register prefetch
//     (NO smem copy-in); whh in regs; h_s double-buffered; h_t stashed to
//     hstash_s for phase B. consF released at END of chunk (last xp read
//     consumed) -- dependency indices still strictly decrease, no deadlock.
//   phase B: li<4: backpressure-wait consF[li+1] >= c-1, then 64 producer
//     dots per thread (W_ih[li] row in regs, reloaded per chunk) -> xpc.
//     li==4: FUSED PROJECTION: 120 threads (o=tid%10, row-group tid/10, 6
//     row-passes) write y directly; no bufA, no proj kernel.
// Residency: 128 thr, ~150 regs (<=168 cap), 26.3 KB smem -> 3 CTAs/SM
// possible = 444 slots >= 320 -> full wave-1 placement.
// ---------------------------------------------------------------------------
__global__ void __launch_bounds__(128, 3)
persist_k(const float* __restrict__ xp0, float* __restrict__ xpc,
          const float* __restrict__ W_ih, const float* __restrict__ W_hh,
          const float* __restrict__ b_ih, const float* __restrict__ b_hh,
          const float* __restrict__ W_out, const float* __restrict__ b_out,
          const float* __restrict__ h0all,
          float* __restrict__ y, float* __restrict__ hfin)
{
    const int li = blockIdx.x >> 6;          // 0..4
    const int b  = blockIdx.x & 63;

    __shared__ __align__(16) float hstash_s[TC_ * H_];  // 25600 B (h_t rows)
    __shared__ __align__(16) float h_s[2][104];         //   832 B

    const int tid = threadIdx.x;
    const int j   = tid;
    const bool act = (j < H_);
    const int jr  = act ? j : 0;

    volatile int* prodF = (volatile int*)g_prodF;
    volatile int* consF = (volatile int*)g_consF;

    // ---- W_hh row in registers, loaded ONCE ----
    ulonglong2 whh[25];
    #pragma unroll
    for (int i = 0; i < 25; i++) { whh[i].x = 0ull; whh[i].y = 0ull; }
    if (act) {
        const ulonglong2* wp = reinterpret_cast<const ulonglong2*>(
            W_hh + ((size_t)li * H_ + j) * H_);
        #pragma unroll
        for (int i = 0; i < 25; i++) whh[i] = wp[i];
        h_s[0][j] = h0all[((size_t)li * B_ + b) * H_ + j];
    }

    float bias2 = 0.0f;                      // producer bias (li<4)
    if (li < L_ - 1 && act)
        bias2 = b_ih[(li + 1) * H_ + j] + b_hh[(li + 1) * H_ + j];

    // fused-projection thread mapping (li==4): o = tid%10, row base tid/10
    const int po = tid % OUT_;
    const int pt = tid / OUT_;               // 0..12 (active if tid < 120)
    const bool qact = (li == L_ - 1) && (tid < 120);
    float biasO = 0.0f;
    if (qact) biasO = b_out[po];

    for (int c = 0; c < NC_; c++) {
        const int t0  = c * TC_;
        const int par = c & 1;

        // ---- acquire xp chunk ----
        if (li > 0) {
            if (tid == 0) {
                while (prodF[li * B_ + b] < c + 1) __nanosleep(64);
            }
            __syncthreads();
            __threadfence();
        }

        const float* xsrc = (li == 0)
            ? xp0 + ((size_t)b * T_ + t0) * H_
            : xpc + (((size_t)par * L_ + li) * B_ + b) * (TC_ * H_);

        // 2-step register prefetch of xp (takes xp off the step's LDS path)
        float x0 = act ? xsrc[0 * H_ + jr] : 0.0f;
        float x1 = act ? xsrc[1 * H_ + jr] : 0.0f;

        // ---- 64 recurrent steps ----
        int cur = 0;
        float th = 0.0f;

        for (int t = 0; t < TC_; t++) {
            const ull a0 = pack2(x0, 0.0f);
            x0 = x1;
            if (act && (t + 2 < TC_)) x1 = xsrc[(t + 2) * H_ + jr];

            const float sum = dot100(
                reinterpret_cast<const ulonglong2*>(h_s[cur]), whh, a0);
            th = fast_tanh(sum);

            if (act) {
                h_s[cur ^ 1][j] = th;
                hstash_s[t * H_ + j] = th;      // stash h_t for phase B
            }
            __syncthreads();
            cur ^= 1;
        }

        // all xp reads of this chunk consumed -> release slot to producer
        if (li > 0 && tid == 0) {
            __threadfence();
            atomicExch(&g_consF[li * B_ + b], c + 1);
        }

        if (act && c == NC_ - 1)
            hfin[((size_t)li * B_ + b) * H_ + j] = th;

        // ---- phase B ----
        if (li < L_ - 1) {
            // backpressure: xpc slot par last read by consumer chunk c-2
            if (c >= 2) {
                if (tid == 0) {
                    while (consF[(li + 1) * B_ + b] < c - 1) __nanosleep(64);
                }
                __syncthreads();
                __threadfence();
            }

            ulonglong2 wih[25];                // reloaded per chunk (L2-hot)
            #pragma unroll
            for (int i = 0; i < 25; i++) { wih[i].x = 0ull; wih[i].y = 0ull; }
            if (act) {
                const ulonglong2* wp = reinterpret_cast<const ulonglong2*>(
                    W_ih + ((size_t)li * H_ + j) * H_);   // W_ih[(li+1)-1]
                #pragma unroll
                for (int i = 0; i < 25; i++) wih[i] = wp[i];
            }

            float* dst = xpc +
                (((size_t)par * L_ + (li + 1)) * B_ + b) * (TC_ * H_);

            #pragma unroll 2
            for (int t = 0; t < TC_; t++) {
                const float sum = dot100(
                    reinterpret_cast<const ulonglong2*>(hstash_s + t * H_),
                    wih, 0ull);
                if (act) dst[t * H_ + j] = bias2 + sum;
            }

            __syncthreads();
            if (tid == 0) {
                __threadfence();
                atomicExch(&g_prodF[(li + 1) * B_ + b], c + 1);
            }
        } else {
            // FUSED PROJECTION: y[b][t0+t][o] = bout[o] + dot(W_out[o], h_t)
            if (qact) {
                ulonglong2 wo[25];             // W_out row po (L2-hot)
                const ulonglong2* wp = reinterpret_cast<const ulonglong2*>(
                    W_out + (size_t)po * H_);
                #pragma unroll
                for (int i = 0; i < 25; i++) wo[i] = wp[i];

                float* yrow = y + ((size_t)b * T_ + t0) * OUT_;
                #pragma unroll
                for (int k = 0; k < 6; k++) {   // rows pt, pt+12, ... (<64)
                    const int t = pt + 12 * k;
                    if (t < TC_) {
                        const float sum = dot100(
                            reinterpret_cast<const ulonglong2*>(
                                hstash_s + t * H_), wo, 0ull);
                        yrow[t * OUT_ + po] = biasO + sum;
                    }
                }
            }
            __syncthreads();   // hstash_s reusable next chunk
        }
    }
}

// ---------------------------------------------------------------------------
// kernel_launch: 3 plain default-stream launches (init flags, layer-0 gemm,
// persistent pipeline with fused projection). Capture-safe APIs only.
// Output: concat( y [B,T,OUT] , h_finals [L,B,H] )
// ---------------------------------------------------------------------------
extern "C" void kernel_launch(void* const* d_in, const int* in_sizes, int n_in,
                              void* d_out, int out_size)
{
    const float* x           = (const float*)d_in[0];
    const float* hidden_prev = (const float*)d_in[1];
    const float* W_ih0       = (const float*)d_in[2];
    const float* W_ih        = (const float*)d_in[3];
    const float* W_hh        = (const float*)d_in[4];
    const float* b_ih        = (const float*)d_in[5];
    const float* b_hh        = (const float*)d_in[6];
    const float* W_out       = (const float*)d_in[7];
    const float* b_out       = (const float*)d_in[8];

    float* out  = (float*)d_out;
    float* y    = out;
    float* hfin = out + (size_t)M_ * OUT_;

    float *xp0, *xpc;
    cudaGetSymbolAddress((void**)&xp0, g_xp0);
    cudaGetSymbolAddress((void**)&xpc, g_xpc);

    // Zero pipeline flags (fresh for every replay).
    init_k<<<1, 512>>>();

    // Layer-0 xp for the whole sequence (depends only on x).
    gemm0_k<<<1024, 256>>>(x, W_ih0, b_ih, b_hh, xp0);

    // Persistent wavefront pipeline: all layers, all chunks, proj fused.
    persist_k<<<L_ * B_, 128>>>(xp0, xpc,
                                W_ih, W_hh, b_ih, b_hh,
                                W_out, b_out,
                                hidden_prev, y, hfin);
}

// round 16
// speedup vs baseline: 2.7156x; 2.7156x over previous
#include <cuda_runtime.h>
#include <cstddef>

using ull = unsigned long long;

// Problem constants
constexpr int B_   = 64;
constexpr int T_   = 2048;
constexpr int H_   = 100;
constexpr int IN_  = 10;
constexpr int OUT_ = 10;
constexpr int L_   = 5;
constexpr int M_   = B_ * T_;          // 131072 rows
constexpr int BUF_ELEMS = M_ * H_;     // 52.4 MB

constexpr int TC_  = 64;               // timesteps per chunk
constexpr int NC_  = T_ / TC_;         // 32 chunks

// Scratch (device globals: no allocation anywhere)
__device__ float g_xp0[BUF_ELEMS];                   // precomputed layer-0 xp
__device__ float g_xpc[2 * L_ * B_ * TC_ * H_];      // xp chunks, parity by c&1
__device__ int   g_prodF[L_ * B_];                   // chunks produced for layer li
__device__ int   g_consF[L_ * B_];                   // chunks consumed by layer li

// ---------------------------------------------------------------------------
// Packed f32x2 helpers (sm_103a FFMA2/FADD2 via PTX)
// ---------------------------------------------------------------------------
__device__ __forceinline__ ull ffma2(ull a, ull b, ull c) {
    ull d;
    asm("fma.rn.f32x2 %0, %1, %2, %3;" : "=l"(d) : "l"(a), "l"(b), "l"(c));
    return d;
}
__device__ __forceinline__ ull addf2(ull a, ull b) {
    ull d;
    asm("add.rn.f32x2 %0, %1, %2;" : "=l"(d) : "l"(a), "l"(b));
    return d;
}
__device__ __forceinline__ ull pack2(float lo, float hi) {
    ull r;
    asm("mov.b64 %0, {%1, %2};" : "=l"(r) : "f"(lo), "f"(hi));
    return r;
}
__device__ __forceinline__ float lo2(ull v) {
    return __uint_as_float((unsigned)(v & 0xFFFFFFFFull));
}
__device__ __forceinline__ float hi2(ull v) {
    return __uint_as_float((unsigned)(v >> 32));
}

// ---------------------------------------------------------------------------
// Fast, overflow-safe tanh (R13-proven): tanh(x) = sign(x)*(1-e)/(1+e),
// e = 2^(-2|x|*log2e) in (0,1].
// ---------------------------------------------------------------------------
__device__ __forceinline__ float fast_tanh(float x) {
    float t = fabsf(x) * -2.8853900817779268f;   // -2*log2(e)*|x|
    float e;
    asm("ex2.approx.f32 %0, %1;" : "=f"(e) : "f"(t));
    float r = __fdividef(1.0f - e, 1.0f + e);
    return copysignf(r, x);
}

// Batched dot over 100 floats: operands smem (broadcast), weights in regs.
__device__ __forceinline__ float dot100(const ulonglong2* __restrict__ hp,
                                        const ulonglong2* __restrict__ w,
                                        ull a0) {
    ull a1 = 0ull, a2 = 0ull, a3 = 0ull;
    ulonglong2 hv[13];
    #pragma unroll
    for (int i = 0; i < 13; i++) hv[i] = hp[i];
    #pragma unroll
    for (int i = 0; i < 13; i++) {
        if (i & 1) { a2 = ffma2(w[i].x, hv[i].x, a2);
                     a3 = ffma2(w[i].y, hv[i].y, a3); }
        else       { a0 = ffma2(w[i].x, hv[i].x, a0);
                     a1 = ffma2(w[i].y, hv[i].y, a1); }
    }
    #pragma unroll
    for (int i = 0; i < 12; i++) hv[i] = hp[13 + i];
    #pragma unroll
    for (int i = 0; i < 12; i++) {
        if (i & 1) { a3 = ffma2(w[13 + i].x, hv[i].x, a3);
                     a2 = ffma2(w[13 + i].y, hv[i].y, a2); }
        else       { a1 = ffma2(w[13 + i].x, hv[i].x, a1);
                     a0 = ffma2(w[13 + i].y, hv[i].y, a0); }
    }
    const ull s = addf2(addf2(a0, a2), addf2(a1, a3));
    return lo2(s) + hi2(s);
}

// ---------------------------------------------------------------------------
// Init: zero the pipeline flags (runs at the head of every replay).
// ---------------------------------------------------------------------------
__global__ void init_k()
{
    const int i = threadIdx.x;
    if (i < L_ * B_) { g_prodF[i] = 0; g_consF[i] = 0; }
}

// ---------------------------------------------------------------------------
// Prologue: layer-0 input GEMM over the ENTIRE sequence (depends only on x).
// ---------------------------------------------------------------------------
__global__ void __launch_bounds__(256)
gemm0_k(const float* __restrict__ A, const float* __restrict__ W,
        const float* __restrict__ b1, const float* __restrict__ b2,
        float* __restrict__ C)
{
    __shared__ __align__(16) float Ws[H_ * IN_];
    __shared__ __align__(16) float As[16 * IN_];

    for (int i = threadIdx.x; i < H_ * IN_; i += 256) Ws[i] = W[i];

    const int c = threadIdx.x & 127;
    const int g = threadIdx.x >> 7;
    const bool act = (c < H_);
    const float bias = act ? (b1[c] + b2[c]) : 0.0f;

    const int tilesTotal = M_ / 16;
    for (int tile = blockIdx.x; tile < tilesTotal; tile += gridDim.x) {
        __syncthreads();
        const float* Arow = A + (size_t)tile * 16 * IN_;
        for (int i = threadIdx.x; i < 16 * IN_; i += 256) As[i] = Arow[i];
        __syncthreads();

        if (act) {
            float acc[8];
            #pragma unroll
            for (int r = 0; r < 8; r++) acc[r] = bias;
            #pragma unroll
            for (int k = 0; k < IN_; k++) {
                const float wv = Ws[c * IN_ + k];
                #pragma unroll
                for (int r = 0; r < 8; r++)
                    acc[r] += wv * As[(g + 2 * r) * IN_ + k];
            }
            #pragma unroll
            for (int r = 0; r < 8; r++)
                C[(size_t)(tile * 16 + g + 2 * r) * H_ + c] = acc[r];
        }
    }
}

// ---------------------------------------------------------------------------
// Persistent pipeline kernel — R13 structure verbatim, with two changes:
//   (1) projection fused into li==4 phase B using SMEM weights (no new
//       register arrays -> step-loop allocation identical to R13), and
//   (2) li==4 no longer stores per-step outputs to global (stash suffices).
// 320 CTAs (li = bid>>6, b = bid&63) x 128 threads; per chunk c:
//   acquire prodF (li>0), copy xp chunk -> xp_s, release consF EARLY,
//   reload whh (per chunk, R13-style), 64 scan steps (stash h_t in xp_s),
//   phase B: li<4 -> producer dots into xpc (wih regs, per-chunk reload);
//            li==4 -> projection to y from xp_s stash + wout_s (smem).
// ---------------------------------------------------------------------------
__global__ void __launch_bounds__(128, 3)
persist_k(const float* __restrict__ xp0, float* __restrict__ xpc,
          const float* __restrict__ W_ih, const float* __restrict__ W_hh,
          const float* __restrict__ b_ih, const float* __restrict__ b_hh,
          const float* __restrict__ W_out, const float* __restrict__ b_out,
          const float* __restrict__ h0all,
          float* __restrict__ y, float* __restrict__ hfin)
{
    const int li = blockIdx.x >> 6;          // 0..4
    const int b  = blockIdx.x & 63;

    __shared__ __align__(16) float xp_s[TC_ * H_];   // 25600 B
    __shared__ __align__(16) float h_s[2][104];      //   832 B
    __shared__ __align__(16) float wout_s[OUT_ * H_];//  4000 B
    __shared__ float bout_s[OUT_];

    const int tid = threadIdx.x;
    const int j   = tid;
    const bool act = (j < H_);
    const int jr  = act ? j : 0;

    volatile int* prodF = (volatile int*)g_prodF;
    volatile int* consF = (volatile int*)g_consF;

    // stage projection weights into smem once (li==4 CTAs only; first use is
    // after several __syncthreads in chunk 0, which order these writes)
    if (li == L_ - 1) {
        for (int i = tid; i < OUT_ * H_; i += 128) wout_s[i] = W_out[i];
        if (tid < OUT_) bout_s[tid] = b_out[tid];
    }

    // h init (once; h_s persists across chunks)
    if (act) h_s[0][j] = h0all[((size_t)li * B_ + b) * H_ + j];

    float bias2 = 0.0f;
    if (li < L_ - 1 && act)
        bias2 = b_ih[(li + 1) * H_ + j] + b_hh[(li + 1) * H_ + j];

    for (int c = 0; c < NC_; c++) {
        const int t0  = c * TC_;
        const int par = c & 1;

        // ---- acquire + copy xp chunk into smem ----
        if (li > 0) {
            if (tid == 0) {
                while (prodF[li * B_ + b] < c + 1) __nanosleep(64);
            }
            __syncthreads();
            __threadfence();
        }
        {
            const float* src = (li == 0)
                ? xp0 + ((size_t)b * T_ + t0) * H_
                : xpc + (((size_t)par * L_ + li) * B_ + b) * (TC_ * H_);
            const float4* s4 = reinterpret_cast<const float4*>(src);
            float4* d4 = reinterpret_cast<float4*>(xp_s);
            for (int i = tid; i < TC_ * H_ / 4; i += 128) d4[i] = s4[i];
        }
        __syncthreads();
        if (li > 0 && tid == 0) {
            __threadfence();
            atomicExch(&g_consF[li * B_ + b], c + 1);
        }

        // ---- W_hh row (reloaded per chunk, R13-style: keeps live ranges
        //      disjoint from wih so regs stay under the 168 cap) ----
        ulonglong2 whh[25];
        #pragma unroll
        for (int i = 0; i < 25; i++) { whh[i].x = 0ull; whh[i].y = 0ull; }
        if (act) {
            const ulonglong2* wp = reinterpret_cast<const ulonglong2*>(
                W_hh + ((size_t)li * H_ + j) * H_);
            #pragma unroll
            for (int i = 0; i < 25; i++) whh[i] = wp[i];
        }
        __syncthreads();   // xp_s ready for all; h_s ready

        // ---- 64 recurrent steps ----
        int cur = 0;
        float th = 0.0f;

        for (int t = 0; t < TC_; t++) {
            const ull a0 = pack2(xp_s[t * H_ + jr], 0.0f);
            const float sum = dot100(
                reinterpret_cast<const ulonglong2*>(h_s[cur]), whh, a0);
            th = fast_tanh(sum);

            if (act) {
                h_s[cur ^ 1][j] = th;
                xp_s[t * H_ + j] = th;                // stash h_t for phase B
            }
            __syncthreads();
            cur ^= 1;
        }

        if (act && c == NC_ - 1)
            hfin[((size_t)li * B_ + b) * H_ + j] = th;

        // ---- phase B ----
        if (li < L_ - 1) {
            // backpressure: slot par was last read by consumer chunk c-2
            if (c >= 2) {
                if (tid == 0) {
                    while (consF[(li + 1) * B_ + b] < c - 1) __nanosleep(64);
                }
                __syncthreads();
                __threadfence();
            }

            ulonglong2 wih[25];
            #pragma unroll
            for (int i = 0; i < 25; i++) { wih[i].x = 0ull; wih[i].y = 0ull; }
            if (act) {
                const ulonglong2* wp = reinterpret_cast<const ulonglong2*>(
                    W_ih + ((size_t)li * H_ + j) * H_);   // W_ih[(li+1)-1]
                #pragma unroll
                for (int i = 0; i < 25; i++) wih[i] = wp[i];
            }

            float* dst = xpc +
                (((size_t)par * L_ + (li + 1)) * B_ + b) * (TC_ * H_);

            #pragma unroll 2
            for (int t = 0; t < TC_; t++) {
                const float sum = dot100(
                    reinterpret_cast<const ulonglong2*>(xp_s + t * H_),
                    wih, 0ull);
                if (act) dst[t * H_ + j] = bias2 + sum;
            }

            __syncthreads();
            if (tid == 0) {
                __threadfence();
                atomicExch(&g_prodF[(li + 1) * B_ + b], c + 1);
            }
        } else {
            // FUSED PROJECTION (smem weights -> no new register arrays):
            // y[b][t0+t][o] = bout[o] + dot(W_out[o,:], h_t)
            if (tid < 120) {
                const int o  = tid % OUT_;        // output column
                const int pt = tid / OUT_;        // row group 0..11
                float* yrow = y + ((size_t)b * T_ + t0) * OUT_;
                const float4* wo4 =
                    reinterpret_cast<const float4*>(wout_s + o * H_);
                const float biasO = bout_s[o];

                for (int t = pt; t < TC_; t += 12) {
                    const float4* hr4 =
                        reinterpret_cast<const float4*>(xp_s + t * H_);
                    float acc = biasO;
                    #pragma unroll
                    for (int k = 0; k < H_ / 4; k++) {
                        const float4 wv = wo4[k];
                        const float4 hv = hr4[k];
                        acc += wv.x * hv.x;
                        acc += wv.y * hv.y;
                        acc += wv.z * hv.z;
                        acc += wv.w * hv.w;
                    }
                    yrow[t * OUT_ + o] = acc;
                }
            }
            __syncthreads();   // xp_s reusable next chunk
        }
    }
}

// ---------------------------------------------------------------------------
// kernel_launch: 3 plain default-stream launches (init flags, layer-0 gemm,
// persistent pipeline with fused projection). Capture-safe APIs only.
// Output: concat( y [B,T,OUT] , h_finals [L,B,H] )
// ---------------------------------------------------------------------------
extern "C" void kernel_launch(void* const* d_in, const int* in_sizes, int n_in,
                              void* d_out, int out_size)
{
    const float* x           = (const float*)d_in[0];
    const float* hidden_prev = (const float*)d_in[1];
    const float* W_ih0       = (const float*)d_in[2];
    const float* W_ih        = (const float*)d_in[3];
    const float* W_hh        = (const float*)d_in[4];
    const float* b_ih        = (const float*)d_in[5];
    const float* b_hh        = (const float*)d_in[6];
    const float* W_out       = (const float*)d_in[7];
    const float* b_out       = (const float*)d_in[8];

    float* out  = (float*)d_out;
    float* y    = out;
    float* hfin = out + (size_t)M_ * OUT_;

    float *xp0, *xpc;
    cudaGetSymbolAddress((void**)&xp0, g_xp0);
    cudaGetSymbolAddress((void**)&xpc, g_xpc);

    // Zero pipeline flags (fresh for every replay).
    init_k<<<1, 512>>>();

    // Layer-0 xp for the whole sequence (depends only on x).
    gemm0_k<<<1024, 256>>>(x, W_ih0, b_ih, b_hh, xp0);

    // Persistent wavefront pipeline: all layers, all chunks, proj fused.
    persist_k<<<L_ * B_, 128>>>(xp0, xpc,
                                W_ih, W_hh, b_ih, b_hh,
                                W_out, b_out,
                                hidden_prev, y, hfin);
}